// round 9
// baseline (speedup 1.0000x reference)
#include <cuda_runtime.h>
#include <cuda_fp16.h>
#include <cstdint>

#define B_DIM 4096
#define SPLIT 32
#define D_DIM 256
#define UNITS 256

#define MTILE 128
#define NTILE 128
#define KC 32
#define NSTAGE (D_DIM / KC)   // 8

// ---------------- smem layout ----------------
#define APITCH 80                       // bytes per 32-elem fp16 row (64B data + 16B pad)
#define ABYTES (128 * APITCH)           // 10240 per buffer (2 buffers)
#define BBYTES (128 * APITCH)           // 10240 per buffer (3 buffers)
#define SM_A 0                          // 2 buffers -> 20480
#define SM_B 20480                      // 3 buffers -> 30720
#define SM_TOTAL (20480 + 30720)        // 51200 -> 2 CTAs/SM

// pre-converted W: fp16 bits, layout [s][n][k] (k contiguous)
__device__ __align__(16) unsigned short g_Wh[SPLIT * UNITS * D_DIM];

// ---------------- helpers ----------------
__device__ __forceinline__ uint32_t smem_u32(const void* p) {
    uint32_t a;
    asm("{ .reg .u64 t; cvta.to.shared.u64 t, %1; cvt.u32.u64 %0, t; }" : "=r"(a) : "l"(p));
    return a;
}

#define STS128(addr, v) \
    asm volatile("st.shared.v4.b32 [%0], {%1,%2,%3,%4};" :: "r"(addr), "r"((v).x), "r"((v).y), "r"((v).z), "r"((v).w) : "memory")

__device__ __forceinline__ void cp16(uint32_t dst, const void* src) {
    asm volatile("cp.async.cg.shared.global [%0], [%1], 16;"
                 :: "r"(dst), "l"((unsigned long long)__cvta_generic_to_global(src)) : "memory");
}
#define CP_COMMIT() asm volatile("cp.async.commit_group;" ::: "memory")
#define CP_WAIT1()  asm volatile("cp.async.wait_group 1;" ::: "memory")

__device__ __forceinline__ void ldsm4(uint32_t* r, uint32_t addr) {
    asm volatile("ldmatrix.sync.aligned.m8n8.x4.shared.b16 {%0,%1,%2,%3}, [%4];"
                 : "=r"(r[0]), "=r"(r[1]), "=r"(r[2]), "=r"(r[3]) : "r"(addr));
}

__device__ __forceinline__ void mma_f16(float* d, const uint32_t* a, const uint32_t* b) {
    asm volatile("mma.sync.aligned.m16n8k16.row.col.f32.f16.f16.f32 "
                 "{%0,%1,%2,%3}, {%4,%5,%6,%7}, {%8,%9}, {%0,%1,%2,%3};"
                 : "+f"(d[0]), "+f"(d[1]), "+f"(d[2]), "+f"(d[3])
                 : "r"(a[0]), "r"(a[1]), "r"(a[2]), "r"(a[3]), "r"(b[0]), "r"(b[1]));
}

// convert 8 fp32 -> 8 packed fp16 (rn)
__device__ __forceinline__ void cvt8(const float4 a, const float4 c, uint4& h) {
    uint32_t p0, p1, p2, p3;
    asm("cvt.rn.f16x2.f32 %0, %1, %2;" : "=r"(p0) : "f"(a.y), "f"(a.x));
    asm("cvt.rn.f16x2.f32 %0, %1, %2;" : "=r"(p1) : "f"(a.w), "f"(a.z));
    asm("cvt.rn.f16x2.f32 %0, %1, %2;" : "=r"(p2) : "f"(c.y), "f"(c.x));
    asm("cvt.rn.f16x2.f32 %0, %1, %2;" : "=r"(p3) : "f"(c.w), "f"(c.z));
    h = make_uint4(p0, p1, p2, p3);
}

// ---------------- prep kernel: W[s][k][n] fp32 -> g_Wh [s][n][k] fp16 ----------------
__global__ void prep_w_kernel(const float* __restrict__ W) {
    __shared__ float tile[32][33];
    int s = blockIdx.z;
    int kb = blockIdx.y * 32;
    int nb = blockIdx.x * 32;
    int tx = threadIdx.x, ty = threadIdx.y;
    const float* Ws = W + (size_t)s * D_DIM * UNITS;
#pragma unroll
    for (int i = 0; i < 4; i++) {
        int k = kb + ty + 8 * i;
        tile[ty + 8 * i][tx] = Ws[(size_t)k * UNITS + nb + tx];
    }
    __syncthreads();
#pragma unroll
    for (int i = 0; i < 4; i++) {
        int n = nb + ty + 8 * i;
        int k = kb + tx;
        g_Wh[((size_t)s * UNITS + n) * D_DIM + k] =
            __half_as_ushort(__float2half_rn(tile[tx][ty + 8 * i]));
    }
}

// ---------------- main GEMM (fp16 HMMA, 4 warps x 64x64 tiles, 2 CTAs/SM) ----------------
__global__ void __launch_bounds__(128, 2) lc_hmma_kernel(
    const float* __restrict__ x, const float* __restrict__ bias, float* __restrict__ out) {
    extern __shared__ char smem[];
    uint32_t sb = smem_u32(smem);
    int tid = threadIdx.x;
    int wid = tid >> 5, lid = tid & 31;
    int mb = blockIdx.x >> 1;       // batch tile
    int nb = blockIdx.x & 1;        // n half (adjacent -> shared x slice hits L2)
    int s  = blockIdx.y;            // split
    int wm = wid >> 1;              // 0..1 : m half (64 rows)
    int wn = wid & 1;               // 0..1 : n half (64 cols)

    float acc[4][8][4];
#pragma unroll
    for (int i = 0; i < 4; i++)
#pragma unroll
        for (int j = 0; j < 8; j++)
#pragma unroll
            for (int v = 0; v < 4; v++) acc[i][j][v] = 0.f;

    // A staging: thread -> full row tid (32 floats)
    const float* xsrc = x + (((size_t)(mb * MTILE + tid) * SPLIT + s) * D_DIM);
    uint32_t asts = sb + SM_A + (uint32_t)(tid * APITCH);

    // B staging: thread -> full n-row tid (32 fp16 = 4 cp16)
    const unsigned short* whsrc = g_Wh + ((size_t)s * UNITS + nb * NTILE + tid) * D_DIM;
    uint32_t bsts = sb + SM_B + (uint32_t)(tid * APITCH);

    // ldmatrix lane offsets
    uint32_t a_off = (uint32_t)((wm * 64 + (lid & 7) + ((lid >> 3) & 1) * 8) * APITCH + (lid >> 4) * 16);
    uint32_t b_off = (uint32_t)((wn * 64 + (lid & 7) + ((lid >> 4) & 1) * 8) * APITCH + ((lid >> 3) & 1) * 16);

    float4 xa[8];

    // ---- prologue ----
#pragma unroll
    for (int j = 0; j < 8; j++) xa[j] = __ldg((const float4*)xsrc + j);
    {
        uint4 h0, h1, h2, h3;
        cvt8(xa[0], xa[1], h0);
        cvt8(xa[2], xa[3], h1);
        cvt8(xa[4], xa[5], h2);
        cvt8(xa[6], xa[7], h3);
        STS128(asts, h0); STS128(asts + 16, h1); STS128(asts + 32, h2); STS128(asts + 48, h3);
    }
    // B chunk 0 -> buf 0 (group 0)
#pragma unroll
    for (int c = 0; c < 4; c++) cp16(bsts + c * 16, whsrc + c * 8);
    CP_COMMIT();
    // B chunk 1 -> buf 1 (group 1)
#pragma unroll
    for (int c = 0; c < 4; c++) cp16(bsts + BBYTES + c * 16, whsrc + KC + c * 8);
    CP_COMMIT();
    // A regs for chunk 1
#pragma unroll
    for (int j = 0; j < 8; j++) xa[j] = __ldg((const float4*)(xsrc + KC) + j);
    CP_WAIT1();
    __syncthreads();

    // ---- main loop over 8 K-chunks ----
#pragma unroll 1
    for (int kc = 0; kc < NSTAGE; kc++) {
        // B cp.async for chunk kc+2
        if (kc + 2 < NSTAGE) {
            uint32_t bd = bsts + (uint32_t)(((kc + 2) % 3) * BBYTES);
            const unsigned short* wh = whsrc + (kc + 2) * KC;
#pragma unroll
            for (int c = 0; c < 4; c++) cp16(bd + c * 16, wh + c * 8);
        }
        CP_COMMIT();

        // A: cvt+STS chunk kc+1 (regs loaded at kc-1)
        if (kc + 1 < NSTAGE) {
            uint4 h0, h1, h2, h3;
            cvt8(xa[0], xa[1], h0);
            cvt8(xa[2], xa[3], h1);
            cvt8(xa[4], xa[5], h2);
            cvt8(xa[6], xa[7], h3);
            uint32_t ad = asts + (uint32_t)(((kc + 1) & 1) * ABYTES);
            STS128(ad, h0); STS128(ad + 16, h1); STS128(ad + 32, h2); STS128(ad + 48, h3);
        }
        // A: LDG regs for chunk kc+2
        if (kc + 2 < NSTAGE) {
#pragma unroll
            for (int j = 0; j < 8; j++) xa[j] = __ldg((const float4*)(xsrc + (kc + 2) * KC) + j);
        }

        // ---- compute chunk kc: 2 k16 steps, warp tile 64x64 ----
        uint32_t abase = sb + SM_A + (uint32_t)((kc & 1) * ABYTES) + a_off;
        uint32_t bbase = sb + SM_B + (uint32_t)((kc % 3) * BBYTES) + b_off;
#pragma unroll
        for (int ks = 0; ks < 2; ks++) {
            uint32_t ab = abase + ks * 32;
            uint32_t bb = bbase + ks * 32;
            uint32_t ah[16], bh[16];
#pragma unroll
            for (int mf = 0; mf < 4; mf++) ldsm4(&ah[4 * mf], ab + mf * 16 * APITCH);
#pragma unroll
            for (int p = 0; p < 4; p++) ldsm4(&bh[4 * p], bb + p * 16 * APITCH);
#pragma unroll
            for (int mf = 0; mf < 4; mf++)
#pragma unroll
                for (int nf = 0; nf < 8; nf++) mma_f16(acc[mf][nf], &ah[4 * mf], &bh[2 * nf]);
        }

        if (kc < NSTAGE - 1) {
            CP_WAIT1();
            __syncthreads();
        }
    }

    // ---- epilogue: bias + relu + store ----
    const float* brow = bias + s * UNITS + nb * NTILE;
#pragma unroll
    for (int mf = 0; mf < 4; mf++) {
        int r0 = mb * MTILE + wm * 64 + mf * 16 + (lid >> 2);
        float* o0 = out + ((size_t)r0 * SPLIT + s) * UNITS + nb * NTILE;
        float* o1 = o0 + (size_t)8 * SPLIT * UNITS;
#pragma unroll
        for (int nf = 0; nf < 8; nf++) {
            int c = wn * 64 + nf * 8 + 2 * (lid & 3);
            float2 bv = *(const float2*)(brow + c);
            float2 v0, v1;
            v0.x = fmaxf(acc[mf][nf][0] + bv.x, 0.f);
            v0.y = fmaxf(acc[mf][nf][1] + bv.y, 0.f);
            v1.x = fmaxf(acc[mf][nf][2] + bv.x, 0.f);
            v1.y = fmaxf(acc[mf][nf][3] + bv.y, 0.f);
            *(float2*)(o0 + c) = v0;
            *(float2*)(o1 + c) = v1;
        }
    }
}

// ---------------- launch ----------------
extern "C" void kernel_launch(void* const* d_in, const int* in_sizes, int n_in,
                              void* d_out, int out_size) {
    const float* x = (const float*)d_in[0];
    const float* W = (const float*)d_in[1];
    const float* b = (const float*)d_in[2];
    float* out = (float*)d_out;

    prep_w_kernel<<<dim3(8, 8, 32), dim3(32, 8)>>>(W);

    cudaFuncSetAttribute(lc_hmma_kernel, cudaFuncAttributeMaxDynamicSharedMemorySize, SM_TOTAL);
    lc_hmma_kernel<<<dim3((B_DIM / MTILE) * 2, SPLIT), 128, SM_TOTAL>>>(x, b, out);
}